// round 3
// baseline (speedup 1.0000x reference)
#include <cuda_runtime.h>
#include <math.h>

// Problem constants
#define BB     8
#define TT     10
#define HW     64
#define NPIX   4096          // 64*64
#define FF     64
#define CO     256           // 4*FF
#define NIMG   80            // B*T

// ---------------- scratch (static device globals; no allocation) -------------
__device__ float g_Zx[(size_t)NIMG * NPIX * CO];   // per-frame input-conv result (+bias)  335 MB
__device__ float g_z [(size_t)BB   * NPIX * CO];   // per-step z = conv(h)+Zx[t]           33 MB
__device__ float g_h [(size_t)BB   * NPIX * FF];   // recurrent hidden state
__device__ float g_c [(size_t)BB   * NPIX * FF];   // cell state
__device__ float g_y1[(size_t)NIMG * NPIX * FF];   // relu(h1) sequence (layer-2 input)    84 MB

// =============================================================================
// Implicit-GEMM direct convolution, SAME padding, NHWC.
//   C[m, n] = sum_k A[m,k] * W[k,n]
//   m = img*4096 + y*64 + x  (BM=64 => one block tile == one image row)
//   k = (ky*KW + kx)*CIN + ci  (matches [kh,kw,Cin,Cout] row-major weights)
// Tiles: BM=64, BN=128, BK=32. 256 threads, each computes 4x8 outputs.
// Epilogue optionally adds bias (batched input conv) or a residual tensor
// (recurrent conv adds the precomputed Zx[t] slice).
// =============================================================================
template<int KH, int KW, int CIN, bool HAS_BIAS>
__global__ __launch_bounds__(256)
void conv_gemm(const float* __restrict__ in,
               const float* __restrict__ wgt,
               const float* __restrict__ bias,
               const float* __restrict__ resid,
               size_t res_img_stride, size_t res_off,
               float* __restrict__ out)
{
    constexpr int K  = KH * KW * CIN;
    constexpr int NT = K / 32;           // K divisible by 32 for all our convs

    __shared__ float As[32][64];         // [k][m], XOR-swizzled columns
    __shared__ float Bs[32][128];        // [k][n]

    const int tid = threadIdx.x;
    const int tm  = tid >> 4;            // 0..15 (M direction)
    const int tn  = tid & 15;            // 0..15 (N direction)

    const int m0  = blockIdx.x * 64;
    const int img = m0 >> 12;
    const int row = (m0 & 4095) >> 6;
    const int n0  = blockIdx.y * 128;

    const float* in_img = in + (size_t)img * NPIX * CIN;

    float acc[4][8];
#pragma unroll
    for (int i = 0; i < 4; ++i)
#pragma unroll
        for (int j = 0; j < 8; ++j) acc[i][j] = 0.f;

    for (int kt = 0; kt < NT; ++kt) {
        const int k0  = kt * 32;
        const int pos = k0 / CIN;        // filter tap index
        const int cib = k0 % CIN;        // ci base within tap
        const int ky  = pos / KW;
        const int kx  = pos % KW;
        const int sy  = row + ky - KH / 2;
        const bool rv = (sy >= 0) && (sy < HW);

        // ---- load A tile: 64 pixels x 32 ci (contiguous float4 along ci) ----
#pragma unroll
        for (int i = 0; i < 2; ++i) {
            int slot = tid + i * 256;            // 0..511
            int pix  = slot >> 3;                // 0..63
            int cq4  = slot & 7;                 // float4 group within 32 ci
            int cq   = cq4 << 2;
            int sx   = pix + kx - KW / 2;
            float4 v = make_float4(0.f, 0.f, 0.f, 0.f);
            if (rv && sx >= 0 && sx < HW)
                v = *reinterpret_cast<const float4*>(
                        in_img + ((size_t)(sy * HW + sx)) * CIN + cib + cq);
            // XOR swizzle columns at float4 granularity: phys group = pixg ^ cq4
            int pixg = pix >> 2, pixl = pix & 3;
            int col  = ((pixg ^ cq4) << 2) | pixl;
            As[cq    ][col] = v.x;
            As[cq + 1][col] = v.y;
            As[cq + 2][col] = v.z;
            As[cq + 3][col] = v.w;
        }
        // ---- load B tile: 32 x 128 weights (row-major [K][256]) -------------
#pragma unroll
        for (int i = 0; i < 4; ++i) {
            int slot = tid + i * 256;            // 0..1023
            int kk   = slot >> 5;
            int nn   = (slot & 31) << 2;
            *reinterpret_cast<float4*>(&Bs[kk][nn]) =
                *reinterpret_cast<const float4*>(wgt + (size_t)(k0 + kk) * CO + n0 + nn);
        }
        __syncthreads();

#pragma unroll
        for (int kk = 0; kk < 32; ++kk) {
            int g = tm ^ ((kk >> 2) & 7);        // undo XOR swizzle
            float4 a  = *reinterpret_cast<const float4*>(&As[kk][g << 2]);
            float4 b0 = *reinterpret_cast<const float4*>(&Bs[kk][tn << 3]);
            float4 b1 = *reinterpret_cast<const float4*>(&Bs[kk][(tn << 3) + 4]);
            float av[4] = {a.x, a.y, a.z, a.w};
            float bv[8] = {b0.x, b0.y, b0.z, b0.w, b1.x, b1.y, b1.z, b1.w};
#pragma unroll
            for (int i = 0; i < 4; ++i)
#pragma unroll
                for (int j = 0; j < 8; ++j)
                    acc[i][j] = fmaf(av[i], bv[j], acc[i][j]);
        }
        __syncthreads();
    }

    // ------------------------------- epilogue --------------------------------
    const float* resb = resid ? (resid + (size_t)img * res_img_stride + res_off) : nullptr;
    const int ncol = n0 + (tn << 3);
#pragma unroll
    for (int i = 0; i < 4; ++i) {
        int m = m0 + (tm << 2) + i;
        int p = m & 4095;
        float v[8];
#pragma unroll
        for (int j = 0; j < 8; ++j) v[j] = acc[i][j];
        if (HAS_BIAS) {
#pragma unroll
            for (int j = 0; j < 8; ++j) v[j] += bias[ncol + j];
        }
        if (resb) {
            const float4 r0 = *reinterpret_cast<const float4*>(resb + (size_t)p * CO + ncol);
            const float4 r1 = *reinterpret_cast<const float4*>(resb + (size_t)p * CO + ncol + 4);
            v[0] += r0.x; v[1] += r0.y; v[2] += r0.z; v[3] += r0.w;
            v[4] += r1.x; v[5] += r1.y; v[6] += r1.z; v[7] += r1.w;
        }
        float4* o = reinterpret_cast<float4*>(out + (size_t)m * CO + ncol);
        o[0] = make_float4(v[0], v[1], v[2], v[3]);
        o[1] = make_float4(v[4], v[5], v[6], v[7]);
    }
}

// =============================================================================
// Pointwise LSTM gate update:
//   z = [zi zf zc zo] (256 ch), c' = hs(zf)*c + hs(zi)*tanh(zc)
//   h' = hs(zo)*tanh(c'),  y = relu(h')
// `first` => c := 0 (t==0), so no memset is needed.
// =============================================================================
__global__ __launch_bounds__(256)
void lstm_point(const float* __restrict__ z, size_t z_img_stride,
                float* __restrict__ c, float* __restrict__ h,
                float* __restrict__ y, size_t y_img_stride, int first)
{
    int idx = blockIdx.x * 256 + threadIdx.x;     // < 8*4096*64
    int f = idx & 63;
    int p = (idx >> 6) & 4095;
    int b = idx >> 18;

    const float* zb = z + (size_t)b * z_img_stride + (size_t)p * CO;
    float zi = zb[f];
    float zf = zb[64 + f];
    float zc = zb[128 + f];
    float zo = zb[192 + f];

    float ig = fminf(fmaxf(fmaf(zi, 0.2f, 0.5f), 0.f), 1.f);
    float fg = fminf(fmaxf(fmaf(zf, 0.2f, 0.5f), 0.f), 1.f);
    float og = fminf(fmaxf(fmaf(zo, 0.2f, 0.5f), 0.f), 1.f);

    float cold = first ? 0.f : c[idx];
    float cn = fg * cold + ig * tanhf(zc);
    float hn = og * tanhf(cn);

    c[idx] = cn;
    h[idx] = hn;
    y[(size_t)b * y_img_stride + (size_t)p * FF + f] = fmaxf(hn, 0.f);
}

// =============================================================================
extern "C" void kernel_launch(void* const* d_in, const int* in_sizes, int n_in,
                              void* d_out, int out_size)
{
    const float* x   = (const float*)d_in[0];
    const float* Wk1 = (const float*)d_in[1];
    const float* Uk1 = (const float*)d_in[2];
    const float* b1  = (const float*)d_in[3];
    const float* Wk2 = (const float*)d_in[4];
    const float* Uk2 = (const float*)d_in[5];
    const float* b2  = (const float*)d_in[6];
    float* out = (float*)d_out;
    (void)in_sizes; (void)n_in; (void)out_size;

    float *Zx, *z, *h, *c, *y1;
    cudaGetSymbolAddress((void**)&Zx, g_Zx);
    cudaGetSymbolAddress((void**)&z,  g_z);
    cudaGetSymbolAddress((void**)&h,  g_h);
    cudaGetSymbolAddress((void**)&c,  g_c);
    cudaGetSymbolAddress((void**)&y1, g_y1);

    const size_t ZIMG = (size_t)NPIX * CO;     // z stride per image
    const size_t ZT   = (size_t)TT * ZIMG;     // Zx stride per batch element
    const size_t YIMG = (size_t)NPIX * FF;
    const size_t YT   = (size_t)TT * YIMG;

    dim3 blk(256);
    dim3 gpre(NIMG * NPIX / 64, 2);            // 5120 x 2
    dim3 grec(BB   * NPIX / 64, 2);            // 512  x 2
    int  pw = BB * NPIX * FF / 256;            // 8192 blocks

    // ---------------- Layer 1 (5x5, Cin=32 / recurrent Cin=64) ----------------
    conv_gemm<5, 5, 32, true><<<gpre, blk>>>(x, Wk1, b1, nullptr, 0, 0, Zx);
    for (int t = 0; t < TT; ++t) {
        const float* zptr; size_t zs;
        if (t == 0) { zptr = Zx; zs = ZT; }    // h0=0 -> z = Zx[t=0] directly
        else {
            conv_gemm<5, 5, 64, false><<<grec, blk>>>(
                h, Uk1, nullptr, Zx, ZT, (size_t)t * ZIMG, z);
            zptr = z; zs = ZIMG;
        }
        lstm_point<<<pw, blk>>>(zptr, zs, c, h, y1 + (size_t)t * YIMG, YT, t == 0);
    }

    // ---------------- Layer 2 (3x3, Cin=64) ----------------------------------
    conv_gemm<3, 3, 64, true><<<gpre, blk>>>(y1, Wk2, b2, nullptr, 0, 0, Zx);
    for (int t = 0; t < TT; ++t) {
        const float* zptr; size_t zs;
        if (t == 0) { zptr = Zx; zs = ZT; }
        else {
            conv_gemm<3, 3, 64, false><<<grec, blk>>>(
                h, Uk2, nullptr, Zx, ZT, (size_t)t * ZIMG, z);
            zptr = z; zs = ZIMG;
        }
        lstm_point<<<pw, blk>>>(zptr, zs, c, h, out + (size_t)t * YIMG, YT, t == 0);
    }
}

// round 6
// speedup vs baseline: 1.0028x; 1.0028x over previous
#include <cuda_runtime.h>
#include <math.h>

// Problem constants
#define BB     8
#define TT     10
#define HW     64
#define NPIX   4096          // 64*64
#define FF     64
#define CO     256           // 4*FF
#define NIMG   80            // B*T

// ---------------- scratch (static device globals; no allocation) -------------
__device__ float g_Zx[(size_t)NIMG * NPIX * CO];   // per-frame input-conv result (+bias)  335 MB
__device__ float g_z [(size_t)BB   * NPIX * CO];   // per-step z = conv(h)+Zx[t]           33 MB
__device__ float g_h [(size_t)BB   * NPIX * FF];   // recurrent hidden state
__device__ float g_c [(size_t)BB   * NPIX * FF];   // cell state
__device__ float g_y1[(size_t)NIMG * NPIX * FF];   // relu(h1) sequence (layer-2 input)    84 MB

// =============================================================================
// Implicit-GEMM direct convolution, SAME padding, NHWC.
//   C[m, n] = sum_k A[m,k] * W[k,n]
//   m = img*4096 + y*64 + x  (BM=64 => one block tile == one image row)
//   k = (ky*KW + kx)*CIN + ci  (matches [kh,kw,Cin,Cout] row-major weights)
// Tiles: BM=64, BN=128, BK=32. 256 threads, each computes 4x8 outputs.
// Epilogue optionally adds bias (batched input conv) or a residual tensor
// (recurrent conv adds the precomputed Zx[t] slice).
// =============================================================================
template<int KH, int KW, int CIN, bool HAS_BIAS>
__global__ __launch_bounds__(256)
void conv_gemm(const float* __restrict__ in,
               const float* __restrict__ wgt,
               const float* __restrict__ bias,
               const float* __restrict__ resid,
               size_t res_img_stride, size_t res_off,
               float* __restrict__ out)
{
    constexpr int K  = KH * KW * CIN;
    constexpr int NT = K / 32;           // K divisible by 32 for all our convs

    __shared__ float As[32][64];         // [k][m], XOR-swizzled columns
    __shared__ float Bs[32][128];        // [k][n]

    const int tid = threadIdx.x;
    const int tm  = tid >> 4;            // 0..15 (M direction)
    const int tn  = tid & 15;            // 0..15 (N direction)

    const int m0  = blockIdx.x * 64;
    const int img = m0 >> 12;
    const int row = (m0 & 4095) >> 6;
    const int n0  = blockIdx.y * 128;

    const float* in_img = in + (size_t)img * NPIX * CIN;

    float acc[4][8];
#pragma unroll
    for (int i = 0; i < 4; ++i)
#pragma unroll
        for (int j = 0; j < 8; ++j) acc[i][j] = 0.f;

    for (int kt = 0; kt < NT; ++kt) {
        const int k0  = kt * 32;
        const int pos = k0 / CIN;        // filter tap index
        const int cib = k0 % CIN;        // ci base within tap
        const int ky  = pos / KW;
        const int kx  = pos % KW;
        const int sy  = row + ky - KH / 2;
        const bool rv = (sy >= 0) && (sy < HW);

        // ---- load A tile: 64 pixels x 32 ci (contiguous float4 along ci) ----
#pragma unroll
        for (int i = 0; i < 2; ++i) {
            int slot = tid + i * 256;            // 0..511
            int pix  = slot >> 3;                // 0..63
            int cq4  = slot & 7;                 // float4 group within 32 ci
            int cq   = cq4 << 2;
            int sx   = pix + kx - KW / 2;
            float4 v = make_float4(0.f, 0.f, 0.f, 0.f);
            if (rv && sx >= 0 && sx < HW)
                v = *reinterpret_cast<const float4*>(
                        in_img + ((size_t)(sy * HW + sx)) * CIN + cib + cq);
            // XOR swizzle columns at float4 granularity: phys group = pixg ^ cq4
            int pixg = pix >> 2, pixl = pix & 3;
            int col  = ((pixg ^ cq4) << 2) | pixl;
            As[cq    ][col] = v.x;
            As[cq + 1][col] = v.y;
            As[cq + 2][col] = v.z;
            As[cq + 3][col] = v.w;
        }
        // ---- load B tile: 32 x 128 weights (row-major [K][256]) -------------
#pragma unroll
        for (int i = 0; i < 4; ++i) {
            int slot = tid + i * 256;            // 0..1023
            int kk   = slot >> 5;
            int nn   = (slot & 31) << 2;
            *reinterpret_cast<float4*>(&Bs[kk][nn]) =
                *reinterpret_cast<const float4*>(wgt + (size_t)(k0 + kk) * CO + n0 + nn);
        }
        __syncthreads();

#pragma unroll
        for (int kk = 0; kk < 32; ++kk) {
            int g = tm ^ ((kk >> 2) & 7);        // undo XOR swizzle
            float4 a  = *reinterpret_cast<const float4*>(&As[kk][g << 2]);
            float4 b0 = *reinterpret_cast<const float4*>(&Bs[kk][tn << 3]);
            float4 b1 = *reinterpret_cast<const float4*>(&Bs[kk][(tn << 3) + 4]);
            float av[4] = {a.x, a.y, a.z, a.w};
            float bv[8] = {b0.x, b0.y, b0.z, b0.w, b1.x, b1.y, b1.z, b1.w};
#pragma unroll
            for (int i = 0; i < 4; ++i)
#pragma unroll
                for (int j = 0; j < 8; ++j)
                    acc[i][j] = fmaf(av[i], bv[j], acc[i][j]);
        }
        __syncthreads();
    }

    // ------------------------------- epilogue --------------------------------
    const float* resb = resid ? (resid + (size_t)img * res_img_stride + res_off) : nullptr;
    const int ncol = n0 + (tn << 3);
#pragma unroll
    for (int i = 0; i < 4; ++i) {
        int m = m0 + (tm << 2) + i;
        int p = m & 4095;
        float v[8];
#pragma unroll
        for (int j = 0; j < 8; ++j) v[j] = acc[i][j];
        if (HAS_BIAS) {
#pragma unroll
            for (int j = 0; j < 8; ++j) v[j] += bias[ncol + j];
        }
        if (resb) {
            const float4 r0 = *reinterpret_cast<const float4*>(resb + (size_t)p * CO + ncol);
            const float4 r1 = *reinterpret_cast<const float4*>(resb + (size_t)p * CO + ncol + 4);
            v[0] += r0.x; v[1] += r0.y; v[2] += r0.z; v[3] += r0.w;
            v[4] += r1.x; v[5] += r1.y; v[6] += r1.z; v[7] += r1.w;
        }
        float4* o = reinterpret_cast<float4*>(out + (size_t)m * CO + ncol);
        o[0] = make_float4(v[0], v[1], v[2], v[3]);
        o[1] = make_float4(v[4], v[5], v[6], v[7]);
    }
}

// =============================================================================
// Pointwise LSTM gate update:
//   z = [zi zf zc zo] (256 ch), c' = hs(zf)*c + hs(zi)*tanh(zc)
//   h' = hs(zo)*tanh(c'),  y = relu(h')
// `first` => c := 0 (t==0), so no memset is needed.
// =============================================================================
__global__ __launch_bounds__(256)
void lstm_point(const float* __restrict__ z, size_t z_img_stride,
                float* __restrict__ c, float* __restrict__ h,
                float* __restrict__ y, size_t y_img_stride, int first)
{
    int idx = blockIdx.x * 256 + threadIdx.x;     // < 8*4096*64
    int f = idx & 63;
    int p = (idx >> 6) & 4095;
    int b = idx >> 18;

    const float* zb = z + (size_t)b * z_img_stride + (size_t)p * CO;
    float zi = zb[f];
    float zf = zb[64 + f];
    float zc = zb[128 + f];
    float zo = zb[192 + f];

    float ig = fminf(fmaxf(fmaf(zi, 0.2f, 0.5f), 0.f), 1.f);
    float fg = fminf(fmaxf(fmaf(zf, 0.2f, 0.5f), 0.f), 1.f);
    float og = fminf(fmaxf(fmaf(zo, 0.2f, 0.5f), 0.f), 1.f);

    float cold = first ? 0.f : c[idx];
    float cn = fg * cold + ig * tanhf(zc);
    float hn = og * tanhf(cn);

    c[idx] = cn;
    h[idx] = hn;
    y[(size_t)b * y_img_stride + (size_t)p * FF + f] = fmaxf(hn, 0.f);
}

// =============================================================================
extern "C" void kernel_launch(void* const* d_in, const int* in_sizes, int n_in,
                              void* d_out, int out_size)
{
    const float* x   = (const float*)d_in[0];
    const float* Wk1 = (const float*)d_in[1];
    const float* Uk1 = (const float*)d_in[2];
    const float* b1  = (const float*)d_in[3];
    const float* Wk2 = (const float*)d_in[4];
    const float* Uk2 = (const float*)d_in[5];
    const float* b2  = (const float*)d_in[6];
    float* out = (float*)d_out;
    (void)in_sizes; (void)n_in; (void)out_size;

    float *Zx, *z, *h, *c, *y1;
    cudaGetSymbolAddress((void**)&Zx, g_Zx);
    cudaGetSymbolAddress((void**)&z,  g_z);
    cudaGetSymbolAddress((void**)&h,  g_h);
    cudaGetSymbolAddress((void**)&c,  g_c);
    cudaGetSymbolAddress((void**)&y1, g_y1);

    const size_t ZIMG = (size_t)NPIX * CO;     // z stride per image
    const size_t ZT   = (size_t)TT * ZIMG;     // Zx stride per batch element
    const size_t YIMG = (size_t)NPIX * FF;
    const size_t YT   = (size_t)TT * YIMG;

    dim3 blk(256);
    dim3 gpre(NIMG * NPIX / 64, 2);            // 5120 x 2
    dim3 grec(BB   * NPIX / 64, 2);            // 512  x 2
    int  pw = BB * NPIX * FF / 256;            // 8192 blocks

    // ---------------- Layer 1 (5x5, Cin=32 / recurrent Cin=64) ----------------
    conv_gemm<5, 5, 32, true><<<gpre, blk>>>(x, Wk1, b1, nullptr, 0, 0, Zx);
    for (int t = 0; t < TT; ++t) {
        const float* zptr; size_t zs;
        if (t == 0) { zptr = Zx; zs = ZT; }    // h0=0 -> z = Zx[t=0] directly
        else {
            conv_gemm<5, 5, 64, false><<<grec, blk>>>(
                h, Uk1, nullptr, Zx, ZT, (size_t)t * ZIMG, z);
            zptr = z; zs = ZIMG;
        }
        lstm_point<<<pw, blk>>>(zptr, zs, c, h, y1 + (size_t)t * YIMG, YT, t == 0);
    }

    // ---------------- Layer 2 (3x3, Cin=64) ----------------------------------
    conv_gemm<3, 3, 64, true><<<gpre, blk>>>(y1, Wk2, b2, nullptr, 0, 0, Zx);
    for (int t = 0; t < TT; ++t) {
        const float* zptr; size_t zs;
        if (t == 0) { zptr = Zx; zs = ZT; }
        else {
            conv_gemm<3, 3, 64, false><<<grec, blk>>>(
                h, Uk2, nullptr, Zx, ZT, (size_t)t * ZIMG, z);
            zptr = z; zs = ZIMG;
        }
        lstm_point<<<pw, blk>>>(zptr, zs, c, h, out + (size_t)t * YIMG, YT, t == 0);
    }
}